// round 1
// baseline (speedup 1.0000x reference)
#include <cuda_runtime.h>
#include <cuda_bf16.h>

// FuzzyLayer: out[b,s,d*I+i] = exp(-(x[b,s,i]-mu[d,i])^2 / sigma[d,i])
// B=16, S=2048, I=256, D=8.
// x: 32 MB read, out: 256 MB write -> HBM-write-bound. Target ~45-60 us.
//
// Strategy:
//  - One thread owns a fixed output column group c4 = d*64 + i4 (4 consecutive i).
//    Params (4 mu, 4 rs=-log2e/sigma) hoisted into registers once per thread.
//  - Block of 512 threads covers ALL 512 column groups -> the 8 'd' values that
//    reuse the same x row are co-resident in one CTA (x served from L1).
//  - Each block processes ROWS=8 consecutive (b,s) rows -> 8 independent
//    LDG.128 per thread (MLP=8).
//  - float4 loads/stores; __stcs streaming stores (zero output reuse).

static constexpr int BATCH = 16;
static constexpr int SEQ   = 2048;
static constexpr int ISZ   = 256;   // INPUT_SIZE
static constexpr int DEG   = 8;     // FUZZY_DEG
static constexpr int BS    = BATCH * SEQ;          // 32768 rows
static constexpr int C4    = DEG * ISZ / 4;        // 512 float4 column groups
static constexpr int ROWS  = 8;                    // rows per block

__device__ __forceinline__ float ex2_approx(float t) {
    float r;
    asm("ex2.approx.ftz.f32 %0, %1;" : "=f"(r) : "f"(t));
    return r;
}

__global__ void __launch_bounds__(512, 2)
fuzzy_kernel(const float4* __restrict__ x4,
             const float4* __restrict__ fp4,
             float4* __restrict__ out4)
{
    const int c4 = threadIdx.x;      // 0..511
    const int i4 = c4 & 63;          // float4 group within I (i = 4*i4)
    const int d  = c4 >> 6;          // fuzzy degree

    // fuzzy_params is (2048, 2) row-major: fp[2j]=mu_j, fp[2j+1]=sigma_j,
    // j = d*256 + i. float4 k holds pairs (2k, 2k+1).
    // For i = 4*i4: pairs j0..j0+3 live in float4 (d*128 + 2*i4) and +1.
    const float4 p0 = fp4[d * 128 + i4 * 2];
    const float4 p1 = fp4[d * 128 + i4 * 2 + 1];

    const float L2E = 1.4426950408889634f;
    const float mu0 = p0.x, rs0 = -L2E / p0.y;
    const float mu1 = p0.z, rs1 = -L2E / p0.w;
    const float mu2 = p1.x, rs2 = -L2E / p1.y;
    const float mu3 = p1.z, rs3 = -L2E / p1.w;

    const int bs0 = blockIdx.x * ROWS;

#pragma unroll
    for (int r = 0; r < ROWS; ++r) {
        const int bs = bs0 + r;
        const float4 xv = __ldg(&x4[bs * 64 + i4]);

        float t0 = xv.x - mu0;
        float t1 = xv.y - mu1;
        float t2 = xv.z - mu2;
        float t3 = xv.w - mu3;
        t0 = t0 * t0 * rs0;
        t1 = t1 * t1 * rs1;
        t2 = t2 * t2 * rs2;
        t3 = t3 * t3 * rs3;

        float4 o;
        o.x = ex2_approx(t0);
        o.y = ex2_approx(t1);
        o.z = ex2_approx(t2);
        o.w = ex2_approx(t3);

        __stcs(&out4[bs * 512 + c4], o);
    }
}

extern "C" void kernel_launch(void* const* d_in, const int* in_sizes, int n_in,
                              void* d_out, int out_size)
{
    const float4* x4  = (const float4*)d_in[0];   // x: (16,2048,256) f32
    const float4* fp4 = (const float4*)d_in[1];   // fuzzy_params: (2048,2) f32
    float4* out4      = (float4*)d_out;           // (16,2048,2048) f32

    dim3 grid(BS / ROWS);   // 4096 blocks
    dim3 block(512);
    fuzzy_kernel<<<grid, block>>>(x4, fp4, out4);
}

// round 2
// speedup vs baseline: 1.0309x; 1.0309x over previous
#include <cuda_runtime.h>
#include <cuda_bf16.h>

// FuzzyLayer: out[b,s,d*I+i] = exp(-(x[b,s,i]-mu[d,i])^2 / sigma[d,i])
// B=16, S=2048, I=256, D=8.  256 MB write + 32 MB read -> HBM-write-bound.
//
// R1 -> R2 change: occupancy 2 CTAs -> 3 CTAs per SM (50% -> 75% warp slots).
// Register pressure cut by prefetching x in 2 batches of 4 rows instead of 8,
// under __launch_bounds__(512, 3) (needs <=42 regs/thread).
// Everything else kept: thread owns fixed column group (params in regs),
// all 8 'd' groups co-resident in CTA (x reuse via L1), float4 traffic,
// __stcs streaming stores (zero output reuse).

static constexpr int BATCH = 16;
static constexpr int SEQ   = 2048;
static constexpr int BS    = BATCH * SEQ;   // 32768 rows
static constexpr int ROWS  = 8;             // rows per block (2 batches of 4)

__device__ __forceinline__ float ex2_approx(float t) {
    float r;
    asm("ex2.approx.ftz.f32 %0, %1;" : "=f"(r) : "f"(t));
    return r;
}

__global__ void __launch_bounds__(512, 3)
fuzzy_kernel(const float4* __restrict__ x4,
             const float4* __restrict__ fp4,
             float4* __restrict__ out4)
{
    const int c4 = threadIdx.x;      // 0..511 : output float4 column group
    const int i4 = c4 & 63;          // float4 group within I
    const int d  = c4 >> 6;          // fuzzy degree

    // fuzzy_params (2048,2) row-major: fp[2j]=mu_j, fp[2j+1]=sigma_j, j=d*256+i.
    const float4 p0 = fp4[d * 128 + i4 * 2];
    const float4 p1 = fp4[d * 128 + i4 * 2 + 1];

    const float L2E = 1.4426950408889634f;
    const float mu0 = p0.x, rs0 = -L2E / p0.y;
    const float mu1 = p0.z, rs1 = -L2E / p0.w;
    const float mu2 = p1.x, rs2 = -L2E / p1.y;
    const float mu3 = p1.z, rs3 = -L2E / p1.w;

    const int bs0 = blockIdx.x * ROWS;
    const float4* __restrict__ xin  = x4   + (size_t)bs0 * 64 + i4;
    float4* __restrict__       oout = out4 + (size_t)bs0 * 512 + c4;

#pragma unroll
    for (int half = 0; half < 2; ++half) {
        // Batch of 4 independent x loads (MLP=4, 16 float regs of payload)
        float4 xa = __ldg(xin + 0 * 64);
        float4 xb = __ldg(xin + 1 * 64);
        float4 xc = __ldg(xin + 2 * 64);
        float4 xd = __ldg(xin + 3 * 64);
        xin += 4 * 64;

#pragma unroll
        for (int r = 0; r < 4; ++r) {
            float4 xv = (r == 0) ? xa : (r == 1) ? xb : (r == 2) ? xc : xd;
            float t0 = xv.x - mu0;
            float t1 = xv.y - mu1;
            float t2 = xv.z - mu2;
            float t3 = xv.w - mu3;
            t0 = t0 * t0 * rs0;
            t1 = t1 * t1 * rs1;
            t2 = t2 * t2 * rs2;
            t3 = t3 * t3 * rs3;

            float4 o;
            o.x = ex2_approx(t0);
            o.y = ex2_approx(t1);
            o.z = ex2_approx(t2);
            o.w = ex2_approx(t3);

            __stcs(oout + r * 512, o);
        }
        oout += 4 * 512;
    }
}

extern "C" void kernel_launch(void* const* d_in, const int* in_sizes, int n_in,
                              void* d_out, int out_size)
{
    const float4* x4  = (const float4*)d_in[0];   // x: (16,2048,256) f32
    const float4* fp4 = (const float4*)d_in[1];   // fuzzy_params: (2048,2) f32
    float4* out4      = (float4*)d_out;           // (16,2048,2048) f32

    fuzzy_kernel<<<BS / ROWS, 512>>>(x4, fp4, out4);
}